// round 4
// baseline (speedup 1.0000x reference)
#include <cuda_runtime.h>

// Trilinear resize [4,128,128,128,2] f32 -> [4,192,192,192,2] f32, zoom=1.5.
// Exact 3-out-per-2-in periodicity, weights {1, 1/3, 2/3}.
// Block = (b, zk, ykp): input strip [3z][5y][128x] in smem, output 192x6x3.
// Each thread owns an output-x PAIR (float4 stores) and one y micro-block.

#define IN_D  128
#define OUT_D 192

__device__ __forceinline__ float2 lerp2(float2 a, float2 b, float wa, float wb) {
    return make_float2(fmaf(a.x, wa, b.x * wb), fmaf(a.y, wa, b.y * wb));
}

__global__ __launch_bounds__(192) void resize_pair_kernel(
    const float2* __restrict__ in,   // [4,128,128,128] voxels (C=2 packed)
    float4* __restrict__ out)        // [4,192,192,96] float4 (x-pairs)
{
    __shared__ float2 tile[15][IN_D];   // [zi*5 + yj][x], 15360 B

    const int blk = blockIdx.x;
    const int ykp = blk & 31;          // y pair-block 0..31
    const int zk  = (blk >> 5) & 63;   // z micro-block 0..63
    const int b   = blk >> 11;

    const int tid = threadIdx.x;       // 0..191

    const float2* base = in + (size_t)b * (IN_D * IN_D * IN_D);

    // ---- Phase 1: cooperative load of 15 input rows (1920 float2) ----
    #pragma unroll
    for (int i = 0; i < 10; i++) {
        int idx = i * 192 + tid;       // 0..1919
        int x = idx & 127;
        int r = idx >> 7;              // 0..14
        int zi = r / 5;
        int yj = r - 5 * zi;
        int z = min(2 * zk + zi, IN_D - 1);
        int y = min(4 * ykp + yj, IN_D - 1);
        tile[r][x] = __ldg(base + ((size_t)z * IN_D + y) * IN_D + x);
    }
    __syncthreads();

    const float c13 = 1.0f / 3.0f;
    const float c23 = 2.0f / 3.0f;

    const int xp = tid % 96;           // output x-pair: x = 2*xp, 2*xp+1
    const int yg = tid / 96;           // which y micro-block of the pair

    // 3-tap x-lerp setup for the output pair, by m = xp % 3
    const int q = xp / 3;
    const int m = xp - 3 * q;
    int i0, i1, i2;
    float a0, a1, w1, w2;
    if (m == 0)      { i0 = 4*q;   i1 = 4*q;   i2 = 4*q+1;
                       a0 = 1.0f; a1 = 0.0f; w1 = c13; w2 = c23; }
    else if (m == 1) { i0 = 4*q+1; i1 = 4*q+2; i2 = 4*q+2;
                       a0 = c23;  a1 = c13;  w1 = 1.0f; w2 = 0.0f; }
    else             { i0 = 4*q+2; i1 = 4*q+3; i2 = min(4*q+4, IN_D-1);
                       a0 = c13;  a1 = c23;  w1 = c23; w2 = c13; }

    // yl2[c][zi][yo]
    float2 yl2[2][3][3];

    #pragma unroll
    for (int zi = 0; zi < 3; zi++) {
        float2 xv0[3], xv1[3];         // x-lerped cols for the 3 input y rows
        #pragma unroll
        for (int yi = 0; yi < 3; yi++) {
            int r = zi * 5 + 2 * yg + yi;
            float2 t0 = tile[r][i0];
            float2 t1 = tile[r][i1];
            float2 t2 = tile[r][i2];
            xv0[yi] = lerp2(t0, t1, a0, a1);
            xv1[yi] = lerp2(t1, t2, w1, w2);
        }
        yl2[0][zi][0] = xv0[0];
        yl2[0][zi][1] = lerp2(xv0[0], xv0[1], c13, c23);
        yl2[0][zi][2] = lerp2(xv0[1], xv0[2], c23, c13);
        yl2[1][zi][0] = xv1[0];
        yl2[1][zi][1] = lerp2(xv1[0], xv1[1], c13, c23);
        yl2[1][zi][2] = lerp2(xv1[1], xv1[2], c23, c13);
    }

    // ---- z-lerp + float4 stores (coalesced: 96 threads x 16B per row) ----
    const int oy0 = 6 * ykp + 3 * yg;
    const int oz0 = 3 * zk;
    size_t ob = (((size_t)b * OUT_D + oz0) * OUT_D + oy0) * 96 + xp;

    #pragma unroll
    for (int zo = 0; zo < 3; zo++) {
        #pragma unroll
        for (int yo = 0; yo < 3; yo++) {
            float2 v0, v1;
            if (zo == 0) {
                v0 = yl2[0][0][yo];
                v1 = yl2[1][0][yo];
            } else if (zo == 1) {
                v0 = lerp2(yl2[0][0][yo], yl2[0][1][yo], c13, c23);
                v1 = lerp2(yl2[1][0][yo], yl2[1][1][yo], c13, c23);
            } else {
                v0 = lerp2(yl2[0][1][yo], yl2[0][2][yo], c23, c13);
                v1 = lerp2(yl2[1][1][yo], yl2[1][2][yo], c23, c13);
            }
            out[ob + ((size_t)zo * OUT_D + yo) * 96] =
                make_float4(v0.x, v0.y, v1.x, v1.y);
        }
    }
}

extern "C" void kernel_launch(void* const* d_in, const int* in_sizes, int n_in,
                              void* d_out, int out_size) {
    const float2* in = (const float2*)d_in[0];
    float4* out = (float4*)d_out;

    int blocks = 4 * 64 * 32;   // (b, zk, ykp) = 8192
    resize_pair_kernel<<<blocks, 192>>>(in, out);
}